// round 5
// baseline (speedup 1.0000x reference)
#include <cuda_runtime.h>
#include <cstdint>
#include <cstddef>

#define BATCH 64
#define DIM 512
#define MAT (DIM * DIM)
#define NUM_ITER 5
#define BK 16
#define NSTAGE (DIM / BK)      // 32
#define PSTRIDE 20             // float2 per smem row (16 + 4 pad): conflict-free

// ---------------- device scratch: all matrices as (hi,lo) float2 ----------------
__device__ float2 g_Y[2][(size_t)BATCH * MAT];
__device__ float2 g_Z[2][(size_t)BATCH * MAT];
__device__ float2 g_T[(size_t)BATCH * MAT];
__device__ float g_norm[BATCH];

// upper-triangular tile pairs for 4x4 grid of 128-wide tiles
__constant__ int c_ti[10] = {0, 0, 0, 0, 1, 1, 1, 2, 2, 3};
__constant__ int c_tj[10] = {0, 1, 2, 3, 1, 2, 3, 2, 3, 3};

// smem: 2 stages x (A plane + B plane), each plane 128 rows x PSTRIDE float2
#define PLANE_F2 (128 * PSTRIDE)          // 2560
#define STAGE_F2 (2 * PLANE_F2)           // 5120
#define SMEM_BYTES (2 * STAGE_F2 * 8)     // 81920

// ---------------- helpers ----------------
__device__ __forceinline__ uint32_t smem_u32(const void* p) {
    uint32_t a;
    asm("{ .reg .u64 t; cvta.to.shared.u64 t, %1; cvt.u32.u64 %0, t; }" : "=r"(a) : "l"(p));
    return a;
}
__device__ __forceinline__ void cp16(uint32_t dst, const void* src) {
    asm volatile("cp.async.cg.shared.global [%0], [%1], 16;" :: "r"(dst), "l"(src));
}
__device__ __forceinline__ float2 split2f(float v) {
    uint32_t h, l;
    asm("cvt.rna.tf32.f32 %0, %1;" : "=r"(h) : "f"(v));
    float hf = __uint_as_float(h);
    asm("cvt.rna.tf32.f32 %0, %1;" : "=r"(l) : "f"(v - hf));
    return make_float2(__uint_as_float(h), __uint_as_float(l));
}
__device__ __forceinline__ void mma8(float* c, uint32_t a0, uint32_t a1, uint32_t a2,
                                     uint32_t a3, uint32_t b0, uint32_t b1) {
    asm volatile(
        "mma.sync.aligned.m16n8k8.row.col.f32.tf32.tf32.f32 "
        "{%0,%1,%2,%3}, {%4,%5,%6,%7}, {%8,%9}, {%0,%1,%2,%3};"
        : "+f"(c[0]), "+f"(c[1]), "+f"(c[2]), "+f"(c[3])
        : "r"(a0), "r"(a1), "r"(a2), "r"(a3), "r"(b0), "r"(b1));
}

// ---------------- Frobenius norm per batch ----------------
__global__ void norm_kernel(const float* __restrict__ x) {
    const int b = blockIdx.x;
    const float4* xb = (const float4*)(x + (size_t)b * MAT);
    float s = 0.f;
    for (int i = threadIdx.x; i < MAT / 4; i += blockDim.x) {
        float4 v = xb[i];
        s += v.x * v.x + v.y * v.y + v.z * v.z + v.w * v.w;
    }
    __shared__ float red[8];
    #pragma unroll
    for (int o = 16; o; o >>= 1) s += __shfl_xor_sync(0xFFFFFFFFu, s, o);
    if ((threadIdx.x & 31) == 0) red[threadIdx.x >> 5] = s;
    __syncthreads();
    if (threadIdx.x < 32) {
        s = (threadIdx.x < (int)(blockDim.x >> 5)) ? red[threadIdx.x] : 0.f;
        #pragma unroll
        for (int o = 16; o; o >>= 1) s += __shfl_xor_sync(0xFFFFFFFFu, s, o);
        if (threadIdx.x == 0) g_norm[b] = sqrtf(s);
    }
}

// ---------------- Y0 = split(x / normA) ----------------
__global__ void init_kernel(const float* __restrict__ x, float2* __restrict__ Y0) {
    const int i = blockIdx.x * blockDim.x + threadIdx.x;
    if (i >= BATCH * MAT / 4) return;
    const int b = i / (MAT / 4);
    const float inv = 1.0f / g_norm[b];
    float4 v = ((const float4*)x)[i];
    float2 p0 = split2f(v.x * inv), p1 = split2f(v.y * inv);
    float2 p2 = split2f(v.z * inv), p3 = split2f(v.w * inv);
    ((float4*)Y0)[2 * i]     = make_float4(p0.x, p0.y, p1.x, p1.y);
    ((float4*)Y0)[2 * i + 1] = make_float4(p2.x, p2.y, p3.x, p3.y);
}

// ---------------- Z1 = T0 = split(1.5 I - 0.5 * Y0) ----------------
__global__ void zt_kernel(const float2* __restrict__ Y0, float2* __restrict__ Z1) {
    const int i = blockIdx.x * blockDim.x + threadIdx.x;   // pair of elements
    if (i >= BATCH * MAT / 2) return;
    float4 y = ((const float4*)Y0)[i];
    const int e0 = (2 * i) % MAT;
    const int row = e0 / DIM, col = e0 % DIM;
    float v0 = -0.5f * (y.x + y.y) + ((row == col)     ? 1.5f : 0.0f);
    float v1 = -0.5f * (y.z + y.w) + ((row == col + 1) ? 1.5f : 0.0f);
    float2 p0 = split2f(v0), p1 = split2f(v1);
    ((float4*)Z1)[i] = make_float4(p0.x, p0.y, p1.x, p1.y);
}

// ---------------- out = (hi + lo) * sqrt(normA) ----------------
__global__ void final_kernel(const float2* __restrict__ Y, float* __restrict__ out) {
    const int i = blockIdx.x * blockDim.x + threadIdx.x;   // pair of elements
    if (i >= BATCH * MAT / 2) return;
    const int b = i / (MAT / 2);
    const float s = sqrtf(g_norm[b]);
    float4 y = ((const float4*)Y)[i];
    ((float2*)out)[i] = make_float2((y.x + y.y) * s, (y.z + y.w) * s);
}

// ---------------- 3xTF32 mma.sync symmetric-output batched GEMM ----------------
// Operands pre-split: each element is float2 (tf32 hi, tf32 lo).
// C = A @ B (MODE 0) or 1.5 I - 0.5 A @ B (MODE 1); all matrices symmetric, so
// B fragments read from B[n][k] and only tiles ti<=tj computed (mirror-stored).
// CTA 128x128, 256 threads (warp tile 64x32), BK=16, 2-stage cp.async.
template <int MODE>
__global__ void __launch_bounds__(256, 2) gemm_tc(const float2* __restrict__ Ag,
                                                  const float2* __restrict__ Bg,
                                                  float2* __restrict__ Cg) {
    extern __shared__ float2 sm[];
    const int b = blockIdx.z;
    const int ti = c_ti[blockIdx.x];
    const int tj = c_tj[blockIdx.x];
    const int bm = ti * 128;
    const int bn = tj * 128;
    const float2* A = Ag + (size_t)b * MAT;
    const float2* B = Bg + (size_t)b * MAT;
    float2*       C = Cg + (size_t)b * MAT;

    const int tid = threadIdx.x;
    const int wid = tid >> 5;
    const int lane = tid & 31;
    const int gid = lane >> 2;   // 0..7
    const int tig = lane & 3;    // 0..3
    const int wm = wid >> 2;     // 0..1
    const int wn = wid & 3;      // 0..3

    const uint32_t s_base = smem_u32(sm);

    // cp.async: per stage, A plane + B plane (B rows are B[n][*] via symmetry)
    auto fill = [&](int buf, int kc) {
        const uint32_t base = s_base + buf * STAGE_F2 * 8;
        const int koff = kc * BK;
        #pragma unroll
        for (int j = 0; j < 4; ++j) {
            const int ch = tid + 256 * j;      // 0..1023
            const int row = ch >> 3;
            const int c2 = (ch & 7) * 2;
            cp16(base + (uint32_t)(row * PSTRIDE + c2) * 8,
                 A + (size_t)(bm + row) * DIM + koff + c2);
            cp16(base + (uint32_t)(PLANE_F2 + row * PSTRIDE + c2) * 8,
                 B + (size_t)(bn + row) * DIM + koff + c2);
        }
        asm volatile("cp.async.commit_group;" ::: "memory");
    };

    float acc[4][4][4];
    #pragma unroll
    for (int mf = 0; mf < 4; ++mf)
        #pragma unroll
        for (int nf = 0; nf < 4; ++nf)
            #pragma unroll
            for (int e = 0; e < 4; ++e) acc[mf][nf][e] = 0.f;

    fill(0, 0);

    for (int s = 0; s < NSTAGE; ++s) {
        if (s > 0) __syncthreads();            // all warps done mma(s-1): buffer free
        if (s + 1 < NSTAGE) {
            fill((s + 1) & 1, s + 1);
            asm volatile("cp.async.wait_group 1;" ::: "memory");
        } else {
            asm volatile("cp.async.wait_group 0;" ::: "memory");
        }
        __syncthreads();

        const uint2* pA = (const uint2*)(sm + (s & 1) * STAGE_F2);
        const uint2* pB = pA + PLANE_F2;

        #pragma unroll
        for (int k8 = 0; k8 < BK / 8; ++k8) {
            const int kb = k8 * 8 + tig;
            uint2 Bf[4][2];
            #pragma unroll
            for (int nf = 0; nf < 4; ++nf) {
                const int r = (wn * 32 + nf * 8 + gid) * PSTRIDE;
                Bf[nf][0] = pB[r + kb];
                Bf[nf][1] = pB[r + kb + 4];
            }
            #pragma unroll
            for (int mf = 0; mf < 4; ++mf) {
                const int r0 = (wm * 64 + mf * 16 + gid) * PSTRIDE;
                const int r1 = r0 + 8 * PSTRIDE;
                uint2 Af[4];
                Af[0] = pA[r0 + kb];
                Af[1] = pA[r1 + kb];
                Af[2] = pA[r0 + kb + 4];
                Af[3] = pA[r1 + kb + 4];
                #pragma unroll
                for (int nf = 0; nf < 4; ++nf) {
                    mma8(acc[mf][nf], Af[0].x, Af[1].x, Af[2].x, Af[3].x,
                         Bf[nf][0].x, Bf[nf][1].x);
                    mma8(acc[mf][nf], Af[0].x, Af[1].x, Af[2].x, Af[3].x,
                         Bf[nf][0].y, Bf[nf][1].y);
                    mma8(acc[mf][nf], Af[0].y, Af[1].y, Af[2].y, Af[3].y,
                         Bf[nf][0].x, Bf[nf][1].x);
                }
            }
        }
    }

    // ---------------- epilogue: split result, main + mirror stores ----------------
    #pragma unroll
    for (int mf = 0; mf < 4; ++mf) {
        #pragma unroll
        for (int nf = 0; nf < 4; ++nf) {
            float* cr = acc[mf][nf];
            const int r0 = bm + wm * 64 + mf * 16 + gid;
            const int r1 = r0 + 8;
            const int cb = bn + wn * 32 + nf * 8 + 2 * tig;
            if (MODE == 1) {
                cr[0] = fmaf(cr[0], -0.5f, (cb == r0)     ? 1.5f : 0.0f);
                cr[1] = fmaf(cr[1], -0.5f, (cb + 1 == r0) ? 1.5f : 0.0f);
                cr[2] = fmaf(cr[2], -0.5f, (cb == r1)     ? 1.5f : 0.0f);
                cr[3] = fmaf(cr[3], -0.5f, (cb + 1 == r1) ? 1.5f : 0.0f);
            }
            float2 p0 = split2f(cr[0]), p1 = split2f(cr[1]);
            float2 p2 = split2f(cr[2]), p3 = split2f(cr[3]);
            *(float4*)(C + (size_t)r0 * DIM + cb) = make_float4(p0.x, p0.y, p1.x, p1.y);
            *(float4*)(C + (size_t)r1 * DIM + cb) = make_float4(p2.x, p2.y, p3.x, p3.y);
            if (ti != tj) {  // mirror transposed
                C[(size_t)cb * DIM + r0]       = p0;
                C[(size_t)(cb + 1) * DIM + r0] = p1;
                C[(size_t)cb * DIM + r1]       = p2;
                C[(size_t)(cb + 1) * DIM + r1] = p3;
            }
        }
    }
}

// ---------------- host launcher ----------------
extern "C" void kernel_launch(void* const* d_in, const int* in_sizes, int n_in,
                              void* d_out, int out_size) {
    const float* x = (const float*)d_in[0];
    float* out = (float*)d_out;

    float2 *Yb, *Zb, *Tb;
    cudaGetSymbolAddress((void**)&Yb, g_Y);
    cudaGetSymbolAddress((void**)&Zb, g_Z);
    cudaGetSymbolAddress((void**)&Tb, g_T);
    const size_t half = (size_t)BATCH * MAT;
    float2* Y[2] = {Yb, Yb + half};
    float2* Z[2] = {Zb, Zb + half};

    cudaFuncSetAttribute(gemm_tc<0>, cudaFuncAttributeMaxDynamicSharedMemorySize, SMEM_BYTES);
    cudaFuncSetAttribute(gemm_tc<1>, cudaFuncAttributeMaxDynamicSharedMemorySize, SMEM_BYTES);

    norm_kernel<<<BATCH, 256>>>(x);
    const int total4 = BATCH * MAT / 4;
    const int total2 = BATCH * MAT / 2;
    init_kernel<<<(total4 + 255) / 256, 256>>>(x, Y[0]);

    // iter 0 (Z0 = I): T0 = 1.5I - 0.5*Y0 stored as Z[0]; Y1 = Y0 @ T0
    zt_kernel<<<(total2 + 255) / 256, 256>>>(Y[0], Z[0]);

    dim3 ggrid(10, 1, BATCH);
    gemm_tc<0><<<ggrid, 256, SMEM_BYTES>>>(Y[0], Z[0], Y[1]);
    int ycur = 1, zcur = 0;

    for (int it = 1; it < NUM_ITER; ++it) {
        gemm_tc<1><<<ggrid, 256, SMEM_BYTES>>>(Z[zcur], Y[ycur], Tb);
        gemm_tc<0><<<ggrid, 256, SMEM_BYTES>>>(Y[ycur], Tb, Y[1 - ycur]);
        ycur ^= 1;
        if (it < NUM_ITER - 1) {
            gemm_tc<0><<<ggrid, 256, SMEM_BYTES>>>(Tb, Z[zcur], Z[1 - zcur]);
            zcur ^= 1;
        }
    }

    final_kernel<<<(total2 + 255) / 256, 256>>>(Y[ycur], out);
}